// round 12
// baseline (speedup 1.0000x reference)
#include <cuda_runtime.h>
#include <mma.h>

using namespace nvcuda;

#define NN 40000
#define NE 640000
#define D  128
#define NL 4

// ---------------- scratch (device globals; no allocation allowed) ----------
__device__ float g_h[NN * D];
__device__ float g_Ah[NN * D];
__device__ float g_Bh[NN * D];
__device__ float g_Dh[NN * D];
__device__ float g_Eh[NN * D];
__device__ float g_hpre[NN * D];
__device__ float g_e[NE * D];
__device__ float g_etmp[NE * D];
__device__ float g_stats[4 * D];   // [h_sum, h_sumsq, e_sum, e_sumsq]
__device__ float g_bn[4 * D];      // [h_mu, h_rstd, e_mu, e_rstd]
// CSR (built once per call; src/dst are layer-invariant)
__device__ int g_cnt[NN];
__device__ int g_cur[NN];
__device__ int g_off[NN + 1];
__device__ int g_eid[NE];

__device__ __forceinline__ float to_tf32(float x)
{
    float r;
    asm("cvt.rna.tf32.f32 %0, %1;" : "=f"(r) : "f"(x));
    return r;
}

// ---------------- packed fp32x2 helpers (sm_103a FFMA2) ----------------------
__device__ __forceinline__ unsigned long long pack2(float x, float y)
{
    unsigned long long r;
    asm("mov.b64 %0, {%1, %2};" : "=l"(r) : "f"(x), "f"(y));
    return r;
}
__device__ __forceinline__ void unpack2(unsigned long long v, float& x, float& y)
{
    asm("mov.b64 {%0, %1}, %2;" : "=f"(x), "=f"(y) : "l"(v));
}
__device__ __forceinline__ unsigned long long ffma2(unsigned long long a,
                                                    unsigned long long b,
                                                    unsigned long long c)
{
    unsigned long long d;
    asm("fma.rn.f32x2 %0, %1, %2, %3;" : "=l"(d) : "l"(a), "l"(b), "l"(c));
    return d;
}

// ---------------- CSR build (once per call) ----------------------------------
__global__ void csr_count_kernel(const int* __restrict__ dst)
{
    int i = blockIdx.x * blockDim.x + threadIdx.x;
    if (i < NE) atomicAdd(&g_cnt[dst[i]], 1);
}

__global__ __launch_bounds__(1024)
void csr_scan_kernel()
{
    __shared__ int sdata[1024];
    __shared__ int carry;
    int tid = threadIdx.x;
    if (tid == 0) carry = 0;
    __syncthreads();
    for (int base = 0; base < NN; base += 1024) {
        int idx = base + tid;
        int v = (idx < NN) ? g_cnt[idx] : 0;
        sdata[tid] = v;
        __syncthreads();
        for (int off = 1; off < 1024; off <<= 1) {
            int t = (tid >= off) ? sdata[tid - off] : 0;
            __syncthreads();
            sdata[tid] += t;
            __syncthreads();
        }
        if (idx < NN) g_off[idx] = carry + sdata[tid] - v;  // exclusive
        __syncthreads();
        if (tid == 1023) carry += sdata[1023];
        __syncthreads();
    }
    if (tid == 0) g_off[NN] = carry;
}

__global__ void csr_fill_kernel(const int* __restrict__ dst)
{
    int i = blockIdx.x * blockDim.x + threadIdx.x;
    if (i < NE) {
        int d = dst[i];
        int slot = g_off[d] + atomicAdd(&g_cur[d], 1);
        g_eid[slot] = i;
    }
}

// ---------------- node GEMM: {Ah,Bh,Dh,Eh} = h @ W[z] + b[z] ----------------
__global__ __launch_bounds__(256)
void node_gemm_kernel(const float* __restrict__ X, const float* __restrict__ Wl,
                      const float* __restrict__ bl, int zbase)
{
    __shared__ float As[32][68];
    __shared__ float Bs[32][128];

    int z = blockIdx.z + zbase;          // 0:A 1:B 2:D 3:E
    int widx = (z < 2) ? z : z + 1;      // W indices {0,1,3,4}
    const float* W    = Wl + widx * D * D;
    const float* bias = bl + widx * D;
    float* C;
    switch (z) { case 0: C = g_Ah; break; case 1: C = g_Bh; break;
                 case 2: C = g_Dh; break; default: C = g_Eh; break; }

    int tid = threadIdx.x;
    int tx = tid & 15, ty = tid >> 4;
    int row0 = blockIdx.x * 64;

    unsigned long long acc2[4][4];
#pragma unroll
    for (int i = 0; i < 4; i++)
#pragma unroll
        for (int j = 0; j < 4; j++) acc2[i][j] = 0ull;

    for (int kc = 0; kc < D; kc += 32) {
#pragma unroll
        for (int p = 0; p < 2; p++) {
            int s = tid + 256 * p;
            int m = s >> 3, kv = (s & 7) << 2;
            float4 v = *(const float4*)(X + (row0 + m) * D + kc + kv);
            As[kv + 0][m] = v.x; As[kv + 1][m] = v.y;
            As[kv + 2][m] = v.z; As[kv + 3][m] = v.w;
        }
#pragma unroll
        for (int p = 0; p < 4; p++) {
            int s = tid + 256 * p;
            int k = s >> 5, cv = (s & 31) << 2;
            *(float4*)&Bs[k][cv] = *(const float4*)(W + (kc + k) * D + cv);
        }
        __syncthreads();
#pragma unroll
        for (int kk = 0; kk < 32; kk++) {
            float4 av = *(const float4*)&As[kk][ty * 4];
            ulonglong2 bp0 = *(const ulonglong2*)&Bs[kk][tx * 8];
            ulonglong2 bp1 = *(const ulonglong2*)&Bs[kk][tx * 8 + 4];
            unsigned long long bq[4] = {bp0.x, bp0.y, bp1.x, bp1.y};
            unsigned long long ad[4];
            ad[0] = pack2(av.x, av.x); ad[1] = pack2(av.y, av.y);
            ad[2] = pack2(av.z, av.z); ad[3] = pack2(av.w, av.w);
#pragma unroll
            for (int i = 0; i < 4; i++)
#pragma unroll
                for (int j = 0; j < 4; j++)
                    acc2[i][j] = ffma2(ad[i], bq[j], acc2[i][j]);
        }
        __syncthreads();
    }

    float4 bi0 = *(const float4*)(bias + tx * 8);
    float4 bi1 = *(const float4*)(bias + tx * 8 + 4);
#pragma unroll
    for (int i = 0; i < 4; i++) {
        float a[8];
#pragma unroll
        for (int j = 0; j < 4; j++) unpack2(acc2[i][j], a[2 * j], a[2 * j + 1]);
        int r = row0 + ty * 4 + i;
        float4 o0 = make_float4(a[0] + bi0.x, a[1] + bi0.y, a[2] + bi0.z, a[3] + bi0.w);
        float4 o1 = make_float4(a[4] + bi1.x, a[5] + bi1.y, a[6] + bi1.z, a[7] + bi1.w);
        *(float4*)(C + r * D + tx * 8)     = o0;
        *(float4*)(C + r * D + tx * 8 + 4) = o1;
    }
}

// ---------------- edge kernel (tf32 WMMA, BM=128): etmp + e-stats only -------
#define AS_STRIDE 36
#define BS_STRIDE 132
#define CS_STRIDE 132
#define AS_FLOATS (128 * AS_STRIDE)
#define BS_FLOATS (32 * BS_STRIDE)
#define CS_FLOATS (128 * CS_STRIDE)
#define AB_FLOATS (AS_FLOATS + BS_FLOATS)
#define EDGE_SMEM_FLOATS (AB_FLOATS > CS_FLOATS ? AB_FLOATS : CS_FLOATS)
#define EDGE_SMEM_BYTES (EDGE_SMEM_FLOATS * 4)

__global__ __launch_bounds__(256)
void edge_gemm_fused(const float* __restrict__ Xe, const float* __restrict__ W,
                     const float* __restrict__ bias,
                     const int* __restrict__ src, const int* __restrict__ dst)
{
    extern __shared__ float sm[];
    float* As = sm;
    float* Bs = sm + AS_FLOATS;
    float* Cs = sm;                         // aliases As/Bs (dead after k-loop)
    __shared__ float s_sum[D], s_sq[D];

    int tid = threadIdx.x;
    if (tid < D) { s_sum[tid] = 0.f; s_sq[tid] = 0.f; }
    int warp = tid >> 5;
    int wm = warp >> 1;
    int wn = warp & 1;
    int row0 = blockIdx.x * 128;

    wmma::fragment<wmma::accumulator, 16, 16, 8, float> cfrag[2][4];
#pragma unroll
    for (int i = 0; i < 2; i++)
#pragma unroll
        for (int j = 0; j < 4; j++) wmma::fill_fragment(cfrag[i][j], 0.f);

    for (int kc = 0; kc < D; kc += 32) {
#pragma unroll
        for (int p = 0; p < 4; p++) {
            int s = tid + 256 * p;
            int m = s >> 3, c4 = (s & 7) << 2;
            float4 v = *(const float4*)(Xe + (row0 + m) * D + kc + c4);
            float* a = As + m * AS_STRIDE + c4;
            a[0] = to_tf32(v.x); a[1] = to_tf32(v.y);
            a[2] = to_tf32(v.z); a[3] = to_tf32(v.w);
        }
#pragma unroll
        for (int p = 0; p < 4; p++) {
            int s = tid + 256 * p;
            int k = s >> 5, c4 = (s & 31) << 2;
            float4 v = *(const float4*)(W + (kc + k) * D + c4);
            float* bptr = Bs + k * BS_STRIDE + c4;
            bptr[0] = to_tf32(v.x); bptr[1] = to_tf32(v.y);
            bptr[2] = to_tf32(v.z); bptr[3] = to_tf32(v.w);
        }
        __syncthreads();
#pragma unroll
        for (int ks = 0; ks < 4; ks++) {
            wmma::fragment<wmma::matrix_a, 16, 16, 8, wmma::precision::tf32, wmma::row_major> af[2];
            wmma::fragment<wmma::matrix_b, 16, 16, 8, wmma::precision::tf32, wmma::row_major> bf[4];
#pragma unroll
            for (int i = 0; i < 2; i++)
                wmma::load_matrix_sync(af[i], As + (wm * 32 + i * 16) * AS_STRIDE + ks * 8, AS_STRIDE);
#pragma unroll
            for (int j = 0; j < 4; j++)
                wmma::load_matrix_sync(bf[j], Bs + ks * 8 * BS_STRIDE + wn * 64 + j * 16, BS_STRIDE);
#pragma unroll
            for (int i = 0; i < 2; i++)
#pragma unroll
                for (int j = 0; j < 4; j++)
                    wmma::mma_sync(cfrag[i][j], af[i], bf[j], cfrag[i][j]);
        }
        __syncthreads();
    }

#pragma unroll
    for (int i = 0; i < 2; i++)
#pragma unroll
        for (int j = 0; j < 4; j++)
            wmma::store_matrix_sync(Cs + (wm * 32 + i * 16) * CS_STRIDE + wn * 64 + j * 16,
                                    cfrag[i][j], CS_STRIDE, wmma::mem_row_major);
    __syncthreads();

    int tx = tid & 15, ty = tid >> 4;
    float4 bi0 = *(const float4*)(bias + tx * 8);
    float4 bi1 = *(const float4*)(bias + tx * 8 + 4);
    float lsum[8], lsq[8];
#pragma unroll
    for (int j = 0; j < 8; j++) { lsum[j] = 0.f; lsq[j] = 0.f; }

#pragma unroll
    for (int i = 0; i < 8; i++) {
        int rl = ty * 8 + i;
        int r  = row0 + rl;
        const float* crow = Cs + rl * CS_STRIDE + tx * 8;
        int sN = src[r], dN = dst[r];
        const float4* dh = (const float4*)(g_Dh + sN * D + tx * 8);
        const float4* eh = (const float4*)(g_Eh + dN * D + tx * 8);
        float4 d0 = dh[0], d1 = dh[1];
        float4 e0 = eh[0], e1 = eh[1];
        float v[8];
        v[0] = crow[0] + bi0.x + d0.x + e0.x;
        v[1] = crow[1] + bi0.y + d0.y + e0.y;
        v[2] = crow[2] + bi0.z + d0.z + e0.z;
        v[3] = crow[3] + bi0.w + d0.w + e0.w;
        v[4] = crow[4] + bi1.x + d1.x + e1.x;
        v[5] = crow[5] + bi1.y + d1.y + e1.y;
        v[6] = crow[6] + bi1.z + d1.z + e1.z;
        v[7] = crow[7] + bi1.w + d1.w + e1.w;
        *(float4*)(g_etmp + (size_t)r * D + tx * 8)     = make_float4(v[0], v[1], v[2], v[3]);
        *(float4*)(g_etmp + (size_t)r * D + tx * 8 + 4) = make_float4(v[4], v[5], v[6], v[7]);
#pragma unroll
        for (int j = 0; j < 8; j++) { lsum[j] += v[j]; lsq[j] += v[j] * v[j]; }
    }

#pragma unroll
    for (int j = 0; j < 8; j++) {
        atomicAdd(&s_sum[tx * 8 + j], lsum[j]);
        atomicAdd(&s_sq[tx * 8 + j],  lsq[j]);
    }
    __syncthreads();
    if (tid < D) {
        atomicAdd(&g_stats[2 * D + tid], s_sum[tid]);
        atomicAdd(&g_stats[3 * D + tid], s_sq[tid]);
    }
}

// ---------------- gather aggregation: hpre = Ah + num/(den+eps) --------------
// One block per dst node, 128 threads (one per feature). Gathers incident
// edges via CSR; recomputes sigma = sigmoid(etmp). Unrolled x2 for MLP.
__global__ __launch_bounds__(128)
void agg_kernel(const int* __restrict__ src)
{
    int v = blockIdx.x;
    int f = threadIdx.x;
    int o   = g_off[v];
    int deg = g_off[v + 1] - o;

    float num0 = 0.f, den0 = 0.f, num1 = 0.f, den1 = 0.f;
    int k = 0;
    for (; k + 1 < deg; k += 2) {
        int e0 = g_eid[o + k], e1 = g_eid[o + k + 1];
        int s0 = src[e0],      s1 = src[e1];
        float x0 = g_etmp[(size_t)e0 * D + f];
        float x1 = g_etmp[(size_t)e1 * D + f];
        float b0 = g_Bh[(size_t)s0 * D + f];
        float b1 = g_Bh[(size_t)s1 * D + f];
        float sg0 = 1.f / (1.f + __expf(-x0));
        float sg1 = 1.f / (1.f + __expf(-x1));
        num0 = fmaf(sg0, b0, num0); den0 += sg0;
        num1 = fmaf(sg1, b1, num1); den1 += sg1;
    }
    if (k < deg) {
        int e0 = g_eid[o + k];
        int s0 = src[e0];
        float x0 = g_etmp[(size_t)e0 * D + f];
        float b0 = g_Bh[(size_t)s0 * D + f];
        float sg0 = 1.f / (1.f + __expf(-x0));
        num0 = fmaf(sg0, b0, num0); den0 += sg0;
    }
    float num = num0 + num1, den = den0 + den1;
    g_hpre[(size_t)v * D + f] = g_Ah[(size_t)v * D + f] + num / (den + 1e-6f);
}

// ---------------- h BN stats from g_hpre --------------------------------------
__global__ __launch_bounds__(256)
void hstats_kernel()
{
    __shared__ float ss[256], sq[256];
    int tid  = threadIdx.x;
    int col  = tid & 127;
    int half = tid >> 7;
    int row0 = blockIdx.x * 64;
    float ls = 0.f, lq = 0.f;
    for (int r = row0 + half; r < row0 + 64; r += 2) {
        float v = g_hpre[(size_t)r * D + col];
        ls += v; lq += v * v;
    }
    ss[tid] = ls; sq[tid] = lq;
    __syncthreads();
    if (tid < 128) {
        atomicAdd(&g_stats[tid],     ss[tid] + ss[tid + 128]);
        atomicAdd(&g_stats[D + tid], sq[tid] + sq[tid + 128]);
    }
}

// ---------------- finalize BN statistics --------------------------------------
__global__ void finalize_stats_kernel()
{
    int c = threadIdx.x;
    float inN = 1.f / (float)NN, inE = 1.f / (float)NE;
    float hmu  = g_stats[c] * inN;
    float hvar = g_stats[D + c] * inN - hmu * hmu;
    g_bn[c]     = hmu;
    g_bn[D + c] = rsqrtf(fmaxf(hvar, 0.f) + 1e-5f);
    float emu  = g_stats[2 * D + c] * inE;
    float evar = g_stats[3 * D + c] * inE - emu * emu;
    g_bn[2 * D + c] = emu;
    g_bn[3 * D + c] = rsqrtf(fmaxf(evar, 0.f) + 1e-5f);
}

// ---------------- h = h_in + relu(bn(h_pre)) -----------------------------------
__global__ __launch_bounds__(256)
void h_apply_kernel(const float* __restrict__ hin, float* __restrict__ hout,
                    const float* __restrict__ gamma, const float* __restrict__ beta)
{
    int i = blockIdx.x * blockDim.x + threadIdx.x;
    if (i >= NN * D / 4) return;
    int c = (i & 31) << 2;
    float4 p  = ((const float4*)g_hpre)[i];
    float4 x  = ((const float4*)hin)[i];
    float4 mu = *(const float4*)(g_bn + c);
    float4 rs = *(const float4*)(g_bn + D + c);
    float4 ga = *(const float4*)(gamma + c);
    float4 be = *(const float4*)(beta + c);
    float4 o;
    o.x = x.x + fmaxf((p.x - mu.x) * rs.x * ga.x + be.x, 0.f);
    o.y = x.y + fmaxf((p.y - mu.y) * rs.y * ga.y + be.y, 0.f);
    o.z = x.z + fmaxf((p.z - mu.z) * rs.z * ga.z + be.z, 0.f);
    o.w = x.w + fmaxf((p.w - mu.w) * rs.w * ga.w + be.w, 0.f);
    ((float4*)hout)[i] = o;
}

// ---------------- e = e_in + relu(bn(e_tmp)) ------------------------------------
__global__ __launch_bounds__(256)
void e_apply_kernel(const float* __restrict__ ein, float* __restrict__ eout,
                    const float* __restrict__ gamma, const float* __restrict__ beta)
{
    int i = blockIdx.x * blockDim.x + threadIdx.x;
    if (i >= NE * D / 4) return;
    int c = (i & 31) << 2;
    float4 p  = ((const float4*)g_etmp)[i];
    float4 x  = ((const float4*)ein)[i];
    float4 mu = *(const float4*)(g_bn + 2 * D + c);
    float4 rs = *(const float4*)(g_bn + 3 * D + c);
    float4 ga = *(const float4*)(gamma + c);
    float4 be = *(const float4*)(beta + c);
    float4 o;
    o.x = x.x + fmaxf((p.x - mu.x) * rs.x * ga.x + be.x, 0.f);
    o.y = x.y + fmaxf((p.y - mu.y) * rs.y * ga.y + be.y, 0.f);
    o.z = x.z + fmaxf((p.z - mu.z) * rs.z * ga.z + be.z, 0.f);
    o.w = x.w + fmaxf((p.w - mu.w) * rs.w * ga.w + be.w, 0.f);
    ((float4*)eout)[i] = o;
}

// ---------------- launcher ------------------------------------------------------
extern "C" void kernel_launch(void* const* d_in, const int* in_sizes, int n_in,
                              void* d_out, int out_size)
{
    const float* h_in  = (const float*)d_in[0];
    const float* e_in  = (const float*)d_in[1];
    const float* W     = (const float*)d_in[2];
    const float* b     = (const float*)d_in[3];
    const float* gamma = (const float*)d_in[4];
    const float* beta  = (const float*)d_in[5];
    const int*   src   = (const int*)d_in[6];
    const int*   dst   = (const int*)d_in[7];
    float* out = (float*)d_out;

    static int init_done = 0;
    static cudaStream_t s1;
    static cudaEvent_t evFork[NL], evJoin[NL];
    if (!init_done) {
        cudaFuncSetAttribute(edge_gemm_fused,
                             cudaFuncAttributeMaxDynamicSharedMemorySize, EDGE_SMEM_BYTES);
        cudaStreamCreateWithFlags(&s1, cudaStreamNonBlocking);
        for (int i = 0; i < NL; i++) {
            cudaEventCreateWithFlags(&evFork[i], cudaEventDisableTiming);
            cudaEventCreateWithFlags(&evJoin[i], cudaEventDisableTiming);
        }
        init_done = 1;
    }

    float *p_stats, *p_h, *p_e;
    int *p_cnt, *p_cur;
    cudaGetSymbolAddress((void**)&p_stats, g_stats);
    cudaGetSymbolAddress((void**)&p_h,     g_h);
    cudaGetSymbolAddress((void**)&p_e,     g_e);
    cudaGetSymbolAddress((void**)&p_cnt,   g_cnt);
    cudaGetSymbolAddress((void**)&p_cur,   g_cur);

    // Output h = h_before (the input h, unchanged by reference semantics)
    cudaMemcpyAsync(out, h_in, (size_t)NN * D * sizeof(float),
                    cudaMemcpyDeviceToDevice, 0);

    // Build CSR once per call (src/dst identical across layers)
    cudaMemsetAsync(p_cnt, 0, NN * sizeof(int), 0);
    cudaMemsetAsync(p_cur, 0, NN * sizeof(int), 0);
    csr_count_kernel<<<(NE + 255) / 256, 256>>>(dst);
    csr_scan_kernel<<<1, 1024>>>();
    csr_fill_kernel<<<(NE + 255) / 256, 256>>>(dst);

    for (int l = 0; l < NL; l++) {
        const float* hcur = (l == 0) ? h_in : p_h;
        const float* ecur = (l == 0) ? e_in : p_e;
        const float* Wl = W + (size_t)l * 5 * D * D;
        const float* bl = b + (size_t)l * 5 * D;
        int last = (l == NL - 1);

        cudaMemsetAsync(p_stats, 0, 4 * D * sizeof(float), 0);

        if (!last)
            node_gemm_kernel<<<dim3(NN / 64, 1, 4), 256>>>(hcur, Wl, bl, 0);
        else  // only Dh, Eh needed for the final edge update
            node_gemm_kernel<<<dim3(NN / 64, 1, 2), 256>>>(hcur, Wl, bl, 2);

        // join: previous layer's e_apply (on s1) must have produced p_e
        if (l > 0)
            cudaStreamWaitEvent(0, evJoin[l - 1], 0);

        edge_gemm_fused<<<NE / 128, 256, EDGE_SMEM_BYTES>>>(
            ecur, Wl + 2 * D * D, bl + 2 * D, src, dst);

        if (!last) {
            agg_kernel<<<NN, 128>>>(src);
            hstats_kernel<<<NN / 64, 256>>>();
        }
        finalize_stats_kernel<<<1, D>>>();

        if (!last) {
            // fork: e_apply on s1 overlaps h_apply + next layer's node GEMM
            cudaEventRecord(evFork[l], 0);
            cudaStreamWaitEvent(s1, evFork[l], 0);
            e_apply_kernel<<<(NE * D / 4 + 255) / 256, 256, 0, s1>>>(
                ecur, p_e, gamma + (size_t)(l * 2 + 1) * D, beta + (size_t)(l * 2 + 1) * D);
            cudaEventRecord(evJoin[l], s1);

            h_apply_kernel<<<(NN * D / 4 + 255) / 256, 256>>>(
                hcur, p_h, gamma + (size_t)(l * 2) * D, beta + (size_t)(l * 2) * D);
        } else {
            e_apply_kernel<<<(NE * D / 4 + 255) / 256, 256>>>(
                ecur, out + (size_t)NN * D,
                gamma + (size_t)(l * 2 + 1) * D, beta + (size_t)(l * 2 + 1) * D);
        }
    }
}

// round 13
// speedup vs baseline: 1.1343x; 1.1343x over previous
#include <cuda_runtime.h>
#include <mma.h>

using namespace nvcuda;

#define NN 40000
#define NE 640000
#define D  128
#define NL 4

// ---------------- scratch (device globals; no allocation allowed) ----------
__device__ float g_h[NN * D];
__device__ float g_Ah[NN * D];
__device__ float g_Bh[NN * D];
__device__ float g_Dh[NN * D];
__device__ float g_Eh[NN * D];
__device__ float g_num[NN * D];
__device__ float g_den[NN * D];
__device__ float g_hpre[NN * D];
__device__ float g_e[NE * D];
__device__ float g_etmp[NE * D];
__device__ float g_stats[4 * D];   // [h_sum, h_sumsq, e_sum, e_sumsq]
__device__ float g_bn[4 * D];      // [h_mu, h_rstd, e_mu, e_rstd]

__device__ __forceinline__ void red_add_v4(float* p, float a, float b, float c, float d)
{
    asm volatile("red.global.add.v4.f32 [%0], {%1, %2, %3, %4};"
                 :: "l"(p), "f"(a), "f"(b), "f"(c), "f"(d) : "memory");
}

__device__ __forceinline__ float to_tf32(float x)
{
    float r;
    asm("cvt.rna.tf32.f32 %0, %1;" : "=f"(r) : "f"(x));
    return r;
}

// ---------------- node GEMM (tf32 WMMA): {Ah,Bh,Dh,Eh} = h @ W[z] + b[z] -----
// BM=64, BN=128, BK=32. 8 warps in 2(m)x4(n); each warp 32x32 via 2x2
// m16n16k8 tf32 fragments. C staging tile aliases As/Bs. grid=(625,1,z).
#define NAS_STRIDE 36
#define NBS_STRIDE 132
#define NCS_STRIDE 132
#define NAS_FLOATS (64 * NAS_STRIDE)
#define NBS_FLOATS (32 * NBS_STRIDE)
#define NCS_FLOATS (64 * NCS_STRIDE)
#define NAB_FLOATS (NAS_FLOATS + NBS_FLOATS)
#define NODE_SMEM_FLOATS (NAB_FLOATS > NCS_FLOATS ? NAB_FLOATS : NCS_FLOATS)
#define NODE_SMEM_BYTES (NODE_SMEM_FLOATS * 4)

__global__ __launch_bounds__(256)
void node_gemm_kernel(const float* __restrict__ X, const float* __restrict__ Wl,
                      const float* __restrict__ bl, int zbase)
{
    extern __shared__ float sm[];
    float* As = sm;                  // [64][36]  (m,k)
    float* Bs = sm + NAS_FLOATS;     // [32][132] (k,n)
    float* Cs = sm;                  // [64][132] aliases As/Bs

    int z = blockIdx.z + zbase;          // 0:A 1:B 2:D 3:E
    int widx = (z < 2) ? z : z + 1;      // W indices {0,1,3,4}
    const float* W    = Wl + widx * D * D;
    const float* bias = bl + widx * D;
    float* C;
    switch (z) { case 0: C = g_Ah; break; case 1: C = g_Bh; break;
                 case 2: C = g_Dh; break; default: C = g_Eh; break; }

    int tid = threadIdx.x;
    int warp = tid >> 5;
    int wm = warp & 1;       // 0..1 (m offset wm*32)
    int wn = warp >> 1;      // 0..3 (n offset wn*32)
    int row0 = blockIdx.x * 64;

    wmma::fragment<wmma::accumulator, 16, 16, 8, float> cfrag[2][2];
#pragma unroll
    for (int i = 0; i < 2; i++)
#pragma unroll
        for (int j = 0; j < 2; j++) wmma::fill_fragment(cfrag[i][j], 0.f);

    for (int kc = 0; kc < D; kc += 32) {
#pragma unroll
        for (int p = 0; p < 2; p++) {
            int s = tid + 256 * p;          // 512 float4
            int m = s >> 3, c4 = (s & 7) << 2;
            float4 v = *(const float4*)(X + (row0 + m) * D + kc + c4);
            float* a = As + m * NAS_STRIDE + c4;
            a[0] = to_tf32(v.x); a[1] = to_tf32(v.y);
            a[2] = to_tf32(v.z); a[3] = to_tf32(v.w);
        }
#pragma unroll
        for (int p = 0; p < 4; p++) {
            int s = tid + 256 * p;          // 1024 float4
            int k = s >> 5, c4 = (s & 31) << 2;
            float4 v = *(const float4*)(W + (kc + k) * D + c4);
            float* bptr = Bs + k * NBS_STRIDE + c4;
            bptr[0] = to_tf32(v.x); bptr[1] = to_tf32(v.y);
            bptr[2] = to_tf32(v.z); bptr[3] = to_tf32(v.w);
        }
        __syncthreads();
#pragma unroll
        for (int ks = 0; ks < 4; ks++) {
            wmma::fragment<wmma::matrix_a, 16, 16, 8, wmma::precision::tf32, wmma::row_major> af[2];
            wmma::fragment<wmma::matrix_b, 16, 16, 8, wmma::precision::tf32, wmma::row_major> bf[2];
#pragma unroll
            for (int i = 0; i < 2; i++)
                wmma::load_matrix_sync(af[i], As + (wm * 32 + i * 16) * NAS_STRIDE + ks * 8, NAS_STRIDE);
#pragma unroll
            for (int j = 0; j < 2; j++)
                wmma::load_matrix_sync(bf[j], Bs + ks * 8 * NBS_STRIDE + wn * 32 + j * 16, NBS_STRIDE);
#pragma unroll
            for (int i = 0; i < 2; i++)
#pragma unroll
                for (int j = 0; j < 2; j++)
                    wmma::mma_sync(cfrag[i][j], af[i], bf[j], cfrag[i][j]);
        }
        __syncthreads();
    }

#pragma unroll
    for (int i = 0; i < 2; i++)
#pragma unroll
        for (int j = 0; j < 2; j++)
            wmma::store_matrix_sync(Cs + (wm * 32 + i * 16) * NCS_STRIDE + wn * 32 + j * 16,
                                    cfrag[i][j], NCS_STRIDE, wmma::mem_row_major);
    __syncthreads();

    int tx = tid & 15, ty = tid >> 4;
    float4 bi0 = *(const float4*)(bias + tx * 8);
    float4 bi1 = *(const float4*)(bias + tx * 8 + 4);
#pragma unroll
    for (int i = 0; i < 4; i++) {
        int rl = ty * 4 + i;
        int r  = row0 + rl;
        const float* crow = Cs + rl * NCS_STRIDE + tx * 8;
        float4 o0 = make_float4(crow[0] + bi0.x, crow[1] + bi0.y,
                                crow[2] + bi0.z, crow[3] + bi0.w);
        float4 o1 = make_float4(crow[4] + bi1.x, crow[5] + bi1.y,
                                crow[6] + bi1.z, crow[7] + bi1.w);
        *(float4*)(C + (size_t)r * D + tx * 8)     = o0;
        *(float4*)(C + (size_t)r * D + tx * 8 + 4) = o1;
    }
}

// ---------------- fused edge kernel (tf32 WMMA, BM=128) ----------------------
#define AS_STRIDE 36
#define BS_STRIDE 132
#define CS_STRIDE 132
#define AS_FLOATS (128 * AS_STRIDE)
#define BS_FLOATS (32 * BS_STRIDE)
#define CS_FLOATS (128 * CS_STRIDE)
#define AB_FLOATS (AS_FLOATS + BS_FLOATS)
#define EDGE_SMEM_FLOATS (AB_FLOATS > CS_FLOATS ? AB_FLOATS : CS_FLOATS)
#define EDGE_SMEM_BYTES (EDGE_SMEM_FLOATS * 4)

__global__ __launch_bounds__(256)
void edge_gemm_fused(const float* __restrict__ Xe, const float* __restrict__ W,
                     const float* __restrict__ bias,
                     const int* __restrict__ src, const int* __restrict__ dst,
                     int do_agg)
{
    extern __shared__ float sm[];
    float* As = sm;
    float* Bs = sm + AS_FLOATS;
    float* Cs = sm;                         // aliases As/Bs
    __shared__ float s_sum[D], s_sq[D];

    int tid = threadIdx.x;
    if (tid < D) { s_sum[tid] = 0.f; s_sq[tid] = 0.f; }
    int warp = tid >> 5;
    int wm = warp >> 1;
    int wn = warp & 1;
    int row0 = blockIdx.x * 128;

    wmma::fragment<wmma::accumulator, 16, 16, 8, float> cfrag[2][4];
#pragma unroll
    for (int i = 0; i < 2; i++)
#pragma unroll
        for (int j = 0; j < 4; j++) wmma::fill_fragment(cfrag[i][j], 0.f);

    for (int kc = 0; kc < D; kc += 32) {
#pragma unroll
        for (int p = 0; p < 4; p++) {
            int s = tid + 256 * p;
            int m = s >> 3, c4 = (s & 7) << 2;
            float4 v = *(const float4*)(Xe + (row0 + m) * D + kc + c4);
            float* a = As + m * AS_STRIDE + c4;
            a[0] = to_tf32(v.x); a[1] = to_tf32(v.y);
            a[2] = to_tf32(v.z); a[3] = to_tf32(v.w);
        }
#pragma unroll
        for (int p = 0; p < 4; p++) {
            int s = tid + 256 * p;
            int k = s >> 5, c4 = (s & 31) << 2;
            float4 v = *(const float4*)(W + (kc + k) * D + c4);
            float* bptr = Bs + k * BS_STRIDE + c4;
            bptr[0] = to_tf32(v.x); bptr[1] = to_tf32(v.y);
            bptr[2] = to_tf32(v.z); bptr[3] = to_tf32(v.w);
        }
        __syncthreads();
#pragma unroll
        for (int ks = 0; ks < 4; ks++) {
            wmma::fragment<wmma::matrix_a, 16, 16, 8, wmma::precision::tf32, wmma::row_major> af[2];
            wmma::fragment<wmma::matrix_b, 16, 16, 8, wmma::precision::tf32, wmma::row_major> bf[4];
#pragma unroll
            for (int i = 0; i < 2; i++)
                wmma::load_matrix_sync(af[i], As + (wm * 32 + i * 16) * AS_STRIDE + ks * 8, AS_STRIDE);
#pragma unroll
            for (int j = 0; j < 4; j++)
                wmma::load_matrix_sync(bf[j], Bs + ks * 8 * BS_STRIDE + wn * 64 + j * 16, BS_STRIDE);
#pragma unroll
            for (int i = 0; i < 2; i++)
#pragma unroll
                for (int j = 0; j < 4; j++)
                    wmma::mma_sync(cfrag[i][j], af[i], bf[j], cfrag[i][j]);
        }
        __syncthreads();
    }

#pragma unroll
    for (int i = 0; i < 2; i++)
#pragma unroll
        for (int j = 0; j < 4; j++)
            wmma::store_matrix_sync(Cs + (wm * 32 + i * 16) * CS_STRIDE + wn * 64 + j * 16,
                                    cfrag[i][j], CS_STRIDE, wmma::mem_row_major);
    __syncthreads();

    int tx = tid & 15, ty = tid >> 4;
    float4 bi0 = *(const float4*)(bias + tx * 8);
    float4 bi1 = *(const float4*)(bias + tx * 8 + 4);
    float lsum[8], lsq[8];
#pragma unroll
    for (int j = 0; j < 8; j++) { lsum[j] = 0.f; lsq[j] = 0.f; }

#pragma unroll
    for (int i = 0; i < 8; i++) {
        int rl = ty * 8 + i;
        int r  = row0 + rl;
        const float* crow = Cs + rl * CS_STRIDE + tx * 8;
        int sN = src[r], dN = dst[r];
        const float4* dh = (const float4*)(g_Dh + (size_t)sN * D + tx * 8);
        const float4* eh = (const float4*)(g_Eh + (size_t)dN * D + tx * 8);
        float4 d0 = dh[0], d1 = dh[1];
        float4 e0 = eh[0], e1 = eh[1];
        float v[8];
        v[0] = crow[0] + bi0.x + d0.x + e0.x;
        v[1] = crow[1] + bi0.y + d0.y + e0.y;
        v[2] = crow[2] + bi0.z + d0.z + e0.z;
        v[3] = crow[3] + bi0.w + d0.w + e0.w;
        v[4] = crow[4] + bi1.x + d1.x + e1.x;
        v[5] = crow[5] + bi1.y + d1.y + e1.y;
        v[6] = crow[6] + bi1.z + d1.z + e1.z;
        v[7] = crow[7] + bi1.w + d1.w + e1.w;
        *(float4*)(g_etmp + (size_t)r * D + tx * 8)     = make_float4(v[0], v[1], v[2], v[3]);
        *(float4*)(g_etmp + (size_t)r * D + tx * 8 + 4) = make_float4(v[4], v[5], v[6], v[7]);
#pragma unroll
        for (int j = 0; j < 8; j++) { lsum[j] += v[j]; lsq[j] += v[j] * v[j]; }
        if (do_agg) {
            const float4* bh = (const float4*)(g_Bh + (size_t)sN * D + tx * 8);
            float4 b0v = bh[0], b1v = bh[1];
            float bb[8] = {b0v.x, b0v.y, b0v.z, b0v.w, b1v.x, b1v.y, b1v.z, b1v.w};
            float sig[8];
#pragma unroll
            for (int j = 0; j < 8; j++) sig[j] = 1.f / (1.f + __expf(-v[j]));
            float* np = g_num + (size_t)dN * D + tx * 8;
            float* dp = g_den + (size_t)dN * D + tx * 8;
            red_add_v4(np,     sig[0] * bb[0], sig[1] * bb[1], sig[2] * bb[2], sig[3] * bb[3]);
            red_add_v4(np + 4, sig[4] * bb[4], sig[5] * bb[5], sig[6] * bb[6], sig[7] * bb[7]);
            red_add_v4(dp,     sig[0], sig[1], sig[2], sig[3]);
            red_add_v4(dp + 4, sig[4], sig[5], sig[6], sig[7]);
        }
    }

#pragma unroll
    for (int j = 0; j < 8; j++) {
        atomicAdd(&s_sum[tx * 8 + j], lsum[j]);
        atomicAdd(&s_sq[tx * 8 + j],  lsq[j]);
    }
    __syncthreads();
    if (tid < D) {
        atomicAdd(&g_stats[2 * D + tid], s_sum[tid]);
        atomicAdd(&g_stats[3 * D + tid], s_sq[tid]);
    }
}

// ---------------- h_pre = Ah + num/(den+eps), + BN stats ---------------------
__global__ __launch_bounds__(256)
void hpre_kernel()
{
    __shared__ float ss[256], sq[256];
    int tid  = threadIdx.x;
    int col  = tid & 127;
    int half = tid >> 7;
    int row0 = blockIdx.x * 64;
    float ls = 0.f, lq = 0.f;
    for (int r = row0 + half; r < row0 + 64; r += 2) {
        int idx = r * D + col;
        float v = g_Ah[idx] + g_num[idx] / (g_den[idx] + 1e-6f);
        g_hpre[idx] = v;
        ls += v; lq += v * v;
    }
    ss[tid] = ls; sq[tid] = lq;
    __syncthreads();
    if (tid < 128) {
        atomicAdd(&g_stats[tid],     ss[tid] + ss[tid + 128]);
        atomicAdd(&g_stats[D + tid], sq[tid] + sq[tid + 128]);
    }
}

// ---------------- finalize BN statistics -------------------------------------
__global__ void finalize_stats_kernel()
{
    int c = threadIdx.x;
    float inN = 1.f / (float)NN, inE = 1.f / (float)NE;
    float hmu  = g_stats[c] * inN;
    float hvar = g_stats[D + c] * inN - hmu * hmu;
    g_bn[c]     = hmu;
    g_bn[D + c] = rsqrtf(fmaxf(hvar, 0.f) + 1e-5f);
    float emu  = g_stats[2 * D + c] * inE;
    float evar = g_stats[3 * D + c] * inE - emu * emu;
    g_bn[2 * D + c] = emu;
    g_bn[3 * D + c] = rsqrtf(fmaxf(evar, 0.f) + 1e-5f);
}

// ---------------- h = h_in + relu(bn(h_pre)) ---------------------------------
__global__ __launch_bounds__(256)
void h_apply_kernel(const float* __restrict__ hin, float* __restrict__ hout,
                    const float* __restrict__ gamma, const float* __restrict__ beta)
{
    int i = blockIdx.x * blockDim.x + threadIdx.x;
    if (i >= NN * D / 4) return;
    int c = (i & 31) << 2;
    float4 p  = ((const float4*)g_hpre)[i];
    float4 x  = ((const float4*)hin)[i];
    float4 mu = *(const float4*)(g_bn + c);
    float4 rs = *(const float4*)(g_bn + D + c);
    float4 ga = *(const float4*)(gamma + c);
    float4 be = *(const float4*)(beta + c);
    float4 o;
    o.x = x.x + fmaxf((p.x - mu.x) * rs.x * ga.x + be.x, 0.f);
    o.y = x.y + fmaxf((p.y - mu.y) * rs.y * ga.y + be.y, 0.f);
    o.z = x.z + fmaxf((p.z - mu.z) * rs.z * ga.z + be.z, 0.f);
    o.w = x.w + fmaxf((p.w - mu.w) * rs.w * ga.w + be.w, 0.f);
    ((float4*)hout)[i] = o;
}

// ---------------- e = e_in + relu(bn(e_tmp)) ----------------------------------
__global__ __launch_bounds__(256)
void e_apply_kernel(const float* __restrict__ ein, float* __restrict__ eout,
                    const float* __restrict__ gamma, const float* __restrict__ beta)
{
    int i = blockIdx.x * blockDim.x + threadIdx.x;
    if (i >= NE * D / 4) return;
    int c = (i & 31) << 2;
    float4 p  = ((const float4*)g_etmp)[i];
    float4 x  = ((const float4*)ein)[i];
    float4 mu = *(const float4*)(g_bn + 2 * D + c);
    float4 rs = *(const float4*)(g_bn + 3 * D + c);
    float4 ga = *(const float4*)(gamma + c);
    float4 be = *(const float4*)(beta + c);
    float4 o;
    o.x = x.x + fmaxf((p.x - mu.x) * rs.x * ga.x + be.x, 0.f);
    o.y = x.y + fmaxf((p.y - mu.y) * rs.y * ga.y + be.y, 0.f);
    o.z = x.z + fmaxf((p.z - mu.z) * rs.z * ga.z + be.z, 0.f);
    o.w = x.w + fmaxf((p.w - mu.w) * rs.w * ga.w + be.w, 0.f);
    ((float4*)eout)[i] = o;
}

// ---------------- launcher ----------------------------------------------------
extern "C" void kernel_launch(void* const* d_in, const int* in_sizes, int n_in,
                              void* d_out, int out_size)
{
    const float* h_in  = (const float*)d_in[0];
    const float* e_in  = (const float*)d_in[1];
    const float* W     = (const float*)d_in[2];
    const float* b     = (const float*)d_in[3];
    const float* gamma = (const float*)d_in[4];
    const float* beta  = (const float*)d_in[5];
    const int*   src   = (const int*)d_in[6];
    const int*   dst   = (const int*)d_in[7];
    float* out = (float*)d_out;

    static int init_done = 0;
    static cudaStream_t s1;
    static cudaEvent_t evFork[NL], evJoin[NL];
    if (!init_done) {
        cudaFuncSetAttribute(edge_gemm_fused,
                             cudaFuncAttributeMaxDynamicSharedMemorySize, EDGE_SMEM_BYTES);
        cudaFuncSetAttribute(node_gemm_kernel,
                             cudaFuncAttributeMaxDynamicSharedMemorySize, NODE_SMEM_BYTES);
        cudaStreamCreateWithFlags(&s1, cudaStreamNonBlocking);
        for (int i = 0; i < NL; i++) {
            cudaEventCreateWithFlags(&evFork[i], cudaEventDisableTiming);
            cudaEventCreateWithFlags(&evJoin[i], cudaEventDisableTiming);
        }
        init_done = 1;
    }

    float *p_num, *p_den, *p_stats, *p_h, *p_e;
    cudaGetSymbolAddress((void**)&p_num,   g_num);
    cudaGetSymbolAddress((void**)&p_den,   g_den);
    cudaGetSymbolAddress((void**)&p_stats, g_stats);
    cudaGetSymbolAddress((void**)&p_h,     g_h);
    cudaGetSymbolAddress((void**)&p_e,     g_e);

    // Output h = h_before (the input h, unchanged by reference semantics)
    cudaMemcpyAsync(out, h_in, (size_t)NN * D * sizeof(float),
                    cudaMemcpyDeviceToDevice, 0);

    for (int l = 0; l < NL; l++) {
        const float* hcur = (l == 0) ? h_in : p_h;
        const float* ecur = (l == 0) ? e_in : p_e;
        const float* Wl = W + (size_t)l * 5 * D * D;
        const float* bl = b + (size_t)l * 5 * D;
        int last = (l == NL - 1);

        cudaMemsetAsync(p_stats, 0, 4 * D * sizeof(float), 0);
        if (!last) {
            cudaMemsetAsync(p_num, 0, (size_t)NN * D * sizeof(float), 0);
            cudaMemsetAsync(p_den, 0, (size_t)NN * D * sizeof(float), 0);
        }

        if (!last)
            node_gemm_kernel<<<dim3(NN / 64, 1, 4), 256, NODE_SMEM_BYTES>>>(hcur, Wl, bl, 0);
        else  // only Dh, Eh needed for the final edge update
            node_gemm_kernel<<<dim3(NN / 64, 1, 2), 256, NODE_SMEM_BYTES>>>(hcur, Wl, bl, 2);

        // join: previous layer's e_apply (on s1) must have produced p_e
        if (l > 0)
            cudaStreamWaitEvent(0, evJoin[l - 1], 0);

        edge_gemm_fused<<<NE / 128, 256, EDGE_SMEM_BYTES>>>(
            ecur, Wl + 2 * D * D, bl + 2 * D, src, dst, last ? 0 : 1);

        if (!last) hpre_kernel<<<NN / 64, 256>>>();
        finalize_stats_kernel<<<1, D>>>();

        if (!last) {
            // fork: e_apply on s1 overlaps h_apply + next layer's node GEMM
            cudaEventRecord(evFork[l], 0);
            cudaStreamWaitEvent(s1, evFork[l], 0);
            e_apply_kernel<<<(NE * D / 4 + 255) / 256, 256, 0, s1>>>(
                ecur, p_e, gamma + (size_t)(l * 2 + 1) * D, beta + (size_t)(l * 2 + 1) * D);
            cudaEventRecord(evJoin[l], s1);

            h_apply_kernel<<<(NN * D / 4 + 255) / 256, 256>>>(
                hcur, p_h, gamma + (size_t)(l * 2) * D, beta + (size_t)(l * 2) * D);
        } else {
            e_apply_kernel<<<(NE * D / 4 + 255) / 256, 256>>>(
                ecur, out + (size_t)NN * D,
                gamma + (size_t)(l * 2 + 1) * D, beta + (size_t)(l * 2 + 1) * D);
        }
    }
}

// round 14
// speedup vs baseline: 1.1486x; 1.0126x over previous
#include <cuda_runtime.h>
#include <mma.h>

using namespace nvcuda;

#define NN 40000
#define NE 640000
#define D  128
#define NL 4

// ---------------- scratch (device globals; no allocation allowed) ----------
__device__ float g_h[NN * D];
__device__ float g_Ah[NN * D];
__device__ float g_Bh[NN * D];
__device__ float g_Dh[NN * D];
__device__ float g_Eh[NN * D];
__device__ float g_num[NN * D];
__device__ float g_den[NN * D];
__device__ float g_hpre[NN * D];
__device__ float g_e[NE * D];
__device__ float g_etmp[NE * D];
__device__ float g_stats[4 * D];   // [h_sum, h_sumsq, e_sum, e_sumsq]
__device__ float g_bn[4 * D];      // [h_mu, h_rstd, e_mu, e_rstd]

__device__ __forceinline__ void red_add_v4(float* p, float a, float b, float c, float d)
{
    asm volatile("red.global.add.v4.f32 [%0], {%1, %2, %3, %4};"
                 :: "l"(p), "f"(a), "f"(b), "f"(c), "f"(d) : "memory");
}

__device__ __forceinline__ float to_tf32(float x)
{
    float r;
    asm("cvt.rna.tf32.f32 %0, %1;" : "=f"(r) : "f"(x));
    return r;
}

// ---------------- node GEMM (tf32 WMMA, BM=128, row-guarded) -----------------
// {Ah,Bh,Dh,Eh}[z] = h @ W[z] + b[z]. BM=128, BN=128, BK=32. 8 warps in
// 4(m)x2(n), 2x4 m16n16k8 fragments. C staging aliases As/Bs. grid=(313,1,z).
#define NAS_STRIDE 36
#define NBS_STRIDE 132
#define NCS_STRIDE 132
#define NAS_FLOATS (128 * NAS_STRIDE)
#define NBS_FLOATS (32 * NBS_STRIDE)
#define NCS_FLOATS (128 * NCS_STRIDE)
#define NAB_FLOATS (NAS_FLOATS + NBS_FLOATS)
#define NODE_SMEM_FLOATS (NAB_FLOATS > NCS_FLOATS ? NAB_FLOATS : NCS_FLOATS)
#define NODE_SMEM_BYTES (NODE_SMEM_FLOATS * 4)
#define NODE_GRID ((NN + 127) / 128)

__global__ __launch_bounds__(256)
void node_gemm_kernel(const float* __restrict__ X, const float* __restrict__ Wl,
                      const float* __restrict__ bl, int zbase)
{
    extern __shared__ float sm[];
    float* As = sm;                  // [128][36] (m,k)
    float* Bs = sm + NAS_FLOATS;     // [32][132] (k,n)
    float* Cs = sm;                  // [128][132] aliases As/Bs

    int z = blockIdx.z + zbase;          // 0:A 1:B 2:D 3:E
    int widx = (z < 2) ? z : z + 1;      // W indices {0,1,3,4}
    const float* W    = Wl + widx * D * D;
    const float* bias = bl + widx * D;
    float* C;
    switch (z) { case 0: C = g_Ah; break; case 1: C = g_Bh; break;
                 case 2: C = g_Dh; break; default: C = g_Eh; break; }

    int tid = threadIdx.x;
    int warp = tid >> 5;
    int wm = warp >> 1;      // 0..3 (m offset wm*32)
    int wn = warp & 1;       // 0..1 (n offset wn*64)
    int row0 = blockIdx.x * 128;

    wmma::fragment<wmma::accumulator, 16, 16, 8, float> cfrag[2][4];
#pragma unroll
    for (int i = 0; i < 2; i++)
#pragma unroll
        for (int j = 0; j < 4; j++) wmma::fill_fragment(cfrag[i][j], 0.f);

    for (int kc = 0; kc < D; kc += 32) {
#pragma unroll
        for (int p = 0; p < 4; p++) {
            int s = tid + 256 * p;          // 1024 float4
            int m = s >> 3, c4 = (s & 7) << 2;
            int r = row0 + m;
            float4 v = (r < NN) ? *(const float4*)(X + (size_t)r * D + kc + c4)
                                : make_float4(0.f, 0.f, 0.f, 0.f);
            float* a = As + m * NAS_STRIDE + c4;
            a[0] = to_tf32(v.x); a[1] = to_tf32(v.y);
            a[2] = to_tf32(v.z); a[3] = to_tf32(v.w);
        }
#pragma unroll
        for (int p = 0; p < 4; p++) {
            int s = tid + 256 * p;          // 1024 float4
            int k = s >> 5, c4 = (s & 31) << 2;
            float4 v = *(const float4*)(W + (kc + k) * D + c4);
            float* bptr = Bs + k * NBS_STRIDE + c4;
            bptr[0] = to_tf32(v.x); bptr[1] = to_tf32(v.y);
            bptr[2] = to_tf32(v.z); bptr[3] = to_tf32(v.w);
        }
        __syncthreads();
#pragma unroll
        for (int ks = 0; ks < 4; ks++) {
            wmma::fragment<wmma::matrix_a, 16, 16, 8, wmma::precision::tf32, wmma::row_major> af[2];
            wmma::fragment<wmma::matrix_b, 16, 16, 8, wmma::precision::tf32, wmma::row_major> bf[4];
#pragma unroll
            for (int i = 0; i < 2; i++)
                wmma::load_matrix_sync(af[i], As + (wm * 32 + i * 16) * NAS_STRIDE + ks * 8, NAS_STRIDE);
#pragma unroll
            for (int j = 0; j < 4; j++)
                wmma::load_matrix_sync(bf[j], Bs + ks * 8 * NBS_STRIDE + wn * 64 + j * 16, NBS_STRIDE);
#pragma unroll
            for (int i = 0; i < 2; i++)
#pragma unroll
                for (int j = 0; j < 4; j++)
                    wmma::mma_sync(cfrag[i][j], af[i], bf[j], cfrag[i][j]);
        }
        __syncthreads();
    }

#pragma unroll
    for (int i = 0; i < 2; i++)
#pragma unroll
        for (int j = 0; j < 4; j++)
            wmma::store_matrix_sync(Cs + (wm * 32 + i * 16) * NCS_STRIDE + wn * 64 + j * 16,
                                    cfrag[i][j], NCS_STRIDE, wmma::mem_row_major);
    __syncthreads();

    int tx = tid & 15, ty = tid >> 4;
    float4 bi0 = *(const float4*)(bias + tx * 8);
    float4 bi1 = *(const float4*)(bias + tx * 8 + 4);
#pragma unroll
    for (int i = 0; i < 8; i++) {
        int rl = ty * 8 + i;
        int r  = row0 + rl;
        if (r >= NN) break;
        const float* crow = Cs + rl * NCS_STRIDE + tx * 8;
        float4 o0 = make_float4(crow[0] + bi0.x, crow[1] + bi0.y,
                                crow[2] + bi0.z, crow[3] + bi0.w);
        float4 o1 = make_float4(crow[4] + bi1.x, crow[5] + bi1.y,
                                crow[6] + bi1.z, crow[7] + bi1.w);
        *(float4*)(C + (size_t)r * D + tx * 8)     = o0;
        *(float4*)(C + (size_t)r * D + tx * 8 + 4) = o1;
    }
}

// ---------------- fused edge kernel (tf32 WMMA, BM=128) ----------------------
#define AS_STRIDE 36
#define BS_STRIDE 132
#define CS_STRIDE 132
#define AS_FLOATS (128 * AS_STRIDE)
#define BS_FLOATS (32 * BS_STRIDE)
#define CS_FLOATS (128 * CS_STRIDE)
#define AB_FLOATS (AS_FLOATS + BS_FLOATS)
#define EDGE_SMEM_FLOATS (AB_FLOATS > CS_FLOATS ? AB_FLOATS : CS_FLOATS)
#define EDGE_SMEM_BYTES (EDGE_SMEM_FLOATS * 4)

__global__ __launch_bounds__(256)
void edge_gemm_fused(const float* __restrict__ Xe, const float* __restrict__ W,
                     const float* __restrict__ bias,
                     const int* __restrict__ src, const int* __restrict__ dst,
                     int do_agg)
{
    extern __shared__ float sm[];
    float* As = sm;
    float* Bs = sm + AS_FLOATS;
    float* Cs = sm;                         // aliases As/Bs
    __shared__ float s_sum[D], s_sq[D];

    int tid = threadIdx.x;
    if (tid < D) { s_sum[tid] = 0.f; s_sq[tid] = 0.f; }
    int warp = tid >> 5;
    int wm = warp >> 1;
    int wn = warp & 1;
    int row0 = blockIdx.x * 128;

    wmma::fragment<wmma::accumulator, 16, 16, 8, float> cfrag[2][4];
#pragma unroll
    for (int i = 0; i < 2; i++)
#pragma unroll
        for (int j = 0; j < 4; j++) wmma::fill_fragment(cfrag[i][j], 0.f);

    for (int kc = 0; kc < D; kc += 32) {
#pragma unroll
        for (int p = 0; p < 4; p++) {
            int s = tid + 256 * p;
            int m = s >> 3, c4 = (s & 7) << 2;
            float4 v = *(const float4*)(Xe + (size_t)(row0 + m) * D + kc + c4);
            float* a = As + m * AS_STRIDE + c4;
            a[0] = to_tf32(v.x); a[1] = to_tf32(v.y);
            a[2] = to_tf32(v.z); a[3] = to_tf32(v.w);
        }
#pragma unroll
        for (int p = 0; p < 4; p++) {
            int s = tid + 256 * p;
            int k = s >> 5, c4 = (s & 31) << 2;
            float4 v = *(const float4*)(W + (kc + k) * D + c4);
            float* bptr = Bs + k * BS_STRIDE + c4;
            bptr[0] = to_tf32(v.x); bptr[1] = to_tf32(v.y);
            bptr[2] = to_tf32(v.z); bptr[3] = to_tf32(v.w);
        }
        __syncthreads();
#pragma unroll
        for (int ks = 0; ks < 4; ks++) {
            wmma::fragment<wmma::matrix_a, 16, 16, 8, wmma::precision::tf32, wmma::row_major> af[2];
            wmma::fragment<wmma::matrix_b, 16, 16, 8, wmma::precision::tf32, wmma::row_major> bf[4];
#pragma unroll
            for (int i = 0; i < 2; i++)
                wmma::load_matrix_sync(af[i], As + (wm * 32 + i * 16) * AS_STRIDE + ks * 8, AS_STRIDE);
#pragma unroll
            for (int j = 0; j < 4; j++)
                wmma::load_matrix_sync(bf[j], Bs + ks * 8 * BS_STRIDE + wn * 64 + j * 16, BS_STRIDE);
#pragma unroll
            for (int i = 0; i < 2; i++)
#pragma unroll
                for (int j = 0; j < 4; j++)
                    wmma::mma_sync(cfrag[i][j], af[i], bf[j], cfrag[i][j]);
        }
        __syncthreads();
    }

#pragma unroll
    for (int i = 0; i < 2; i++)
#pragma unroll
        for (int j = 0; j < 4; j++)
            wmma::store_matrix_sync(Cs + (wm * 32 + i * 16) * CS_STRIDE + wn * 64 + j * 16,
                                    cfrag[i][j], CS_STRIDE, wmma::mem_row_major);
    __syncthreads();

    int tx = tid & 15, ty = tid >> 4;
    float4 bi0 = *(const float4*)(bias + tx * 8);
    float4 bi1 = *(const float4*)(bias + tx * 8 + 4);
    float lsum[8], lsq[8];
#pragma unroll
    for (int j = 0; j < 8; j++) { lsum[j] = 0.f; lsq[j] = 0.f; }

#pragma unroll
    for (int i = 0; i < 8; i++) {
        int rl = ty * 8 + i;
        int r  = row0 + rl;
        const float* crow = Cs + rl * CS_STRIDE + tx * 8;
        int sN = src[r], dN = dst[r];
        const float4* dh = (const float4*)(g_Dh + (size_t)sN * D + tx * 8);
        const float4* eh = (const float4*)(g_Eh + (size_t)dN * D + tx * 8);
        float4 d0 = dh[0], d1 = dh[1];
        float4 e0 = eh[0], e1 = eh[1];
        float v[8];
        v[0] = crow[0] + bi0.x + d0.x + e0.x;
        v[1] = crow[1] + bi0.y + d0.y + e0.y;
        v[2] = crow[2] + bi0.z + d0.z + e0.z;
        v[3] = crow[3] + bi0.w + d0.w + e0.w;
        v[4] = crow[4] + bi1.x + d1.x + e1.x;
        v[5] = crow[5] + bi1.y + d1.y + e1.y;
        v[6] = crow[6] + bi1.z + d1.z + e1.z;
        v[7] = crow[7] + bi1.w + d1.w + e1.w;
        *(float4*)(g_etmp + (size_t)r * D + tx * 8)     = make_float4(v[0], v[1], v[2], v[3]);
        *(float4*)(g_etmp + (size_t)r * D + tx * 8 + 4) = make_float4(v[4], v[5], v[6], v[7]);
#pragma unroll
        for (int j = 0; j < 8; j++) { lsum[j] += v[j]; lsq[j] += v[j] * v[j]; }
        if (do_agg) {
            const float4* bh = (const float4*)(g_Bh + (size_t)sN * D + tx * 8);
            float4 b0v = bh[0], b1v = bh[1];
            float bb[8] = {b0v.x, b0v.y, b0v.z, b0v.w, b1v.x, b1v.y, b1v.z, b1v.w};
            float sig[8];
#pragma unroll
            for (int j = 0; j < 8; j++) sig[j] = 1.f / (1.f + __expf(-v[j]));
            float* np = g_num + (size_t)dN * D + tx * 8;
            float* dp = g_den + (size_t)dN * D + tx * 8;
            red_add_v4(np,     sig[0] * bb[0], sig[1] * bb[1], sig[2] * bb[2], sig[3] * bb[3]);
            red_add_v4(np + 4, sig[4] * bb[4], sig[5] * bb[5], sig[6] * bb[6], sig[7] * bb[7]);
            red_add_v4(dp,     sig[0], sig[1], sig[2], sig[3]);
            red_add_v4(dp + 4, sig[4], sig[5], sig[6], sig[7]);
        }
    }

#pragma unroll
    for (int j = 0; j < 8; j++) {
        atomicAdd(&s_sum[tx * 8 + j], lsum[j]);
        atomicAdd(&s_sq[tx * 8 + j],  lsq[j]);
    }
    __syncthreads();
    if (tid < D) {
        atomicAdd(&g_stats[2 * D + tid], s_sum[tid]);
        atomicAdd(&g_stats[3 * D + tid], s_sq[tid]);
    }
}

// ---------------- h_pre = Ah + num/(den+eps), + BN stats ---------------------
__global__ __launch_bounds__(256)
void hpre_kernel()
{
    __shared__ float ss[256], sq[256];
    int tid  = threadIdx.x;
    int col  = tid & 127;
    int half = tid >> 7;
    int row0 = blockIdx.x * 64;
    float ls = 0.f, lq = 0.f;
    for (int r = row0 + half; r < row0 + 64; r += 2) {
        int idx = r * D + col;
        float v = g_Ah[idx] + g_num[idx] / (g_den[idx] + 1e-6f);
        g_hpre[idx] = v;
        ls += v; lq += v * v;
    }
    ss[tid] = ls; sq[tid] = lq;
    __syncthreads();
    if (tid < 128) {
        atomicAdd(&g_stats[tid],     ss[tid] + ss[tid + 128]);
        atomicAdd(&g_stats[D + tid], sq[tid] + sq[tid + 128]);
    }
}

// ---------------- finalize BN statistics -------------------------------------
__global__ void finalize_stats_kernel()
{
    int c = threadIdx.x;
    float inN = 1.f / (float)NN, inE = 1.f / (float)NE;
    float hmu  = g_stats[c] * inN;
    float hvar = g_stats[D + c] * inN - hmu * hmu;
    g_bn[c]     = hmu;
    g_bn[D + c] = rsqrtf(fmaxf(hvar, 0.f) + 1e-5f);
    float emu  = g_stats[2 * D + c] * inE;
    float evar = g_stats[3 * D + c] * inE - emu * emu;
    g_bn[2 * D + c] = emu;
    g_bn[3 * D + c] = rsqrtf(fmaxf(evar, 0.f) + 1e-5f);
}

// ---------------- h = h_in + relu(bn(h_pre)) ---------------------------------
__global__ __launch_bounds__(256)
void h_apply_kernel(const float* __restrict__ hin, float* __restrict__ hout,
                    const float* __restrict__ gamma, const float* __restrict__ beta)
{
    int i = blockIdx.x * blockDim.x + threadIdx.x;
    if (i >= NN * D / 4) return;
    int c = (i & 31) << 2;
    float4 p  = ((const float4*)g_hpre)[i];
    float4 x  = ((const float4*)hin)[i];
    float4 mu = *(const float4*)(g_bn + c);
    float4 rs = *(const float4*)(g_bn + D + c);
    float4 ga = *(const float4*)(gamma + c);
    float4 be = *(const float4*)(beta + c);
    float4 o;
    o.x = x.x + fmaxf((p.x - mu.x) * rs.x * ga.x + be.x, 0.f);
    o.y = x.y + fmaxf((p.y - mu.y) * rs.y * ga.y + be.y, 0.f);
    o.z = x.z + fmaxf((p.z - mu.z) * rs.z * ga.z + be.z, 0.f);
    o.w = x.w + fmaxf((p.w - mu.w) * rs.w * ga.w + be.w, 0.f);
    ((float4*)hout)[i] = o;
}

// ---------------- e = e_in + relu(bn(e_tmp)) ----------------------------------
__global__ __launch_bounds__(256)
void e_apply_kernel(const float* __restrict__ ein, float* __restrict__ eout,
                    const float* __restrict__ gamma, const float* __restrict__ beta)
{
    int i = blockIdx.x * blockDim.x + threadIdx.x;
    if (i >= NE * D / 4) return;
    int c = (i & 31) << 2;
    float4 p  = ((const float4*)g_etmp)[i];
    float4 x  = ((const float4*)ein)[i];
    float4 mu = *(const float4*)(g_bn + 2 * D + c);
    float4 rs = *(const float4*)(g_bn + 3 * D + c);
    float4 ga = *(const float4*)(gamma + c);
    float4 be = *(const float4*)(beta + c);
    float4 o;
    o.x = x.x + fmaxf((p.x - mu.x) * rs.x * ga.x + be.x, 0.f);
    o.y = x.y + fmaxf((p.y - mu.y) * rs.y * ga.y + be.y, 0.f);
    o.z = x.z + fmaxf((p.z - mu.z) * rs.z * ga.z + be.z, 0.f);
    o.w = x.w + fmaxf((p.w - mu.w) * rs.w * ga.w + be.w, 0.f);
    ((float4*)eout)[i] = o;
}

// ---------------- launcher ----------------------------------------------------
extern "C" void kernel_launch(void* const* d_in, const int* in_sizes, int n_in,
                              void* d_out, int out_size)
{
    const float* h_in  = (const float*)d_in[0];
    const float* e_in  = (const float*)d_in[1];
    const float* W     = (const float*)d_in[2];
    const float* b     = (const float*)d_in[3];
    const float* gamma = (const float*)d_in[4];
    const float* beta  = (const float*)d_in[5];
    const int*   src   = (const int*)d_in[6];
    const int*   dst   = (const int*)d_in[7];
    float* out = (float*)d_out;

    static int init_done = 0;
    static cudaStream_t s1;
    static cudaEvent_t evFork[NL], evJoin[NL];
    if (!init_done) {
        cudaFuncSetAttribute(edge_gemm_fused,
                             cudaFuncAttributeMaxDynamicSharedMemorySize, EDGE_SMEM_BYTES);
        cudaFuncSetAttribute(node_gemm_kernel,
                             cudaFuncAttributeMaxDynamicSharedMemorySize, NODE_SMEM_BYTES);
        cudaStreamCreateWithFlags(&s1, cudaStreamNonBlocking);
        for (int i = 0; i < NL; i++) {
            cudaEventCreateWithFlags(&evFork[i], cudaEventDisableTiming);
            cudaEventCreateWithFlags(&evJoin[i], cudaEventDisableTiming);
        }
        init_done = 1;
    }

    float *p_num, *p_den, *p_stats, *p_h, *p_e;
    cudaGetSymbolAddress((void**)&p_num,   g_num);
    cudaGetSymbolAddress((void**)&p_den,   g_den);
    cudaGetSymbolAddress((void**)&p_stats, g_stats);
    cudaGetSymbolAddress((void**)&p_h,     g_h);
    cudaGetSymbolAddress((void**)&p_e,     g_e);

    // Output h = h_before (the input h, unchanged by reference semantics)
    cudaMemcpyAsync(out, h_in, (size_t)NN * D * sizeof(float),
                    cudaMemcpyDeviceToDevice, 0);

    for (int l = 0; l < NL; l++) {
        const float* hcur = (l == 0) ? h_in : p_h;
        const float* ecur = (l == 0) ? e_in : p_e;
        const float* Wl = W + (size_t)l * 5 * D * D;
        const float* bl = b + (size_t)l * 5 * D;
        int last = (l == NL - 1);

        cudaMemsetAsync(p_stats, 0, 4 * D * sizeof(float), 0);
        if (!last) {
            cudaMemsetAsync(p_num, 0, (size_t)NN * D * sizeof(float), 0);
            cudaMemsetAsync(p_den, 0, (size_t)NN * D * sizeof(float), 0);
        }

        if (!last)
            node_gemm_kernel<<<dim3(NODE_GRID, 1, 4), 256, NODE_SMEM_BYTES>>>(hcur, Wl, bl, 0);
        else  // only Dh, Eh needed for the final edge update
            node_gemm_kernel<<<dim3(NODE_GRID, 1, 2), 256, NODE_SMEM_BYTES>>>(hcur, Wl, bl, 2);

        // join: previous layer's e_apply (on s1) must have produced p_e
        if (l > 0)
            cudaStreamWaitEvent(0, evJoin[l - 1], 0);

        edge_gemm_fused<<<NE / 128, 256, EDGE_SMEM_BYTES>>>(
            ecur, Wl + 2 * D * D, bl + 2 * D, src, dst, last ? 0 : 1);

        if (!last) hpre_kernel<<<NN / 64, 256>>>();
        finalize_stats_kernel<<<1, D>>>();

        if (!last) {
            // fork: e_apply on s1 overlaps h_apply + next layer's node GEMM
            cudaEventRecord(evFork[l], 0);
            cudaStreamWaitEvent(s1, evFork[l], 0);
            e_apply_kernel<<<(NE * D / 4 + 255) / 256, 256, 0, s1>>>(
                ecur, p_e, gamma + (size_t)(l * 2 + 1) * D, beta + (size_t)(l * 2 + 1) * D);
            cudaEventRecord(evJoin[l], s1);

            h_apply_kernel<<<(NN * D / 4 + 255) / 256, 256>>>(
                hcur, p_h, gamma + (size_t)(l * 2) * D, beta + (size_t)(l * 2) * D);
        } else {
            e_apply_kernel<<<(NE * D / 4 + 255) / 256, 256>>>(
                ecur, out + (size_t)NN * D,
                gamma + (size_t)(l * 2 + 1) * D, beta + (size_t)(l * 2 + 1) * D);
        }
    }
}